// round 2
// baseline (speedup 1.0000x reference)
#include <cuda_runtime.h>

#define MAX_N 100000
#define D 64

// Scratch (device globals: sanctioned alternative to cudaMalloc)
__device__ float g_h[MAX_N * D];     // h = x @ W^T
__device__ float g_deg[MAX_N];
__device__ float g_dinv[MAX_N];

// ---------------------------------------------------------------------------
// 1) degree init: every node gets a self-loop -> deg starts at 1
// ---------------------------------------------------------------------------
__global__ void deg_init_kernel(int N) {
    int i = blockIdx.x * blockDim.x + threadIdx.x;
    if (i < N) g_deg[i] = 1.0f;
}

// 2) accumulate in-degree over edge dst (edge_index is int32: JAX default
//    x64-disabled config downcasts the requested int64 silently)
__global__ void deg_acc_kernel(const int* __restrict__ ei, int E) {
    int e = blockIdx.x * blockDim.x + threadIdx.x;
    if (e < E) {
        int d = ei[E + e];   // edge_index[1][e]
        atomicAdd(&g_deg[d], 1.0f);
    }
}

// 3) dinv = rsqrt(deg)   (deg >= 1 always, no zero guard needed)
__global__ void dinv_kernel(int N) {
    int i = blockIdx.x * blockDim.x + threadIdx.x;
    if (i < N) g_dinv[i] = rsqrtf(g_deg[i]);
}

// ---------------------------------------------------------------------------
// 4) GEMM: h[n][o] = sum_i x[n][i] * W[o][i]
//    Epilogue: out[n][o] = h[n][o] * dinv[n]^2 + b[o]   (self-loop + bias,
//    fully initializes the poisoned output buffer)
// ---------------------------------------------------------------------------
__global__ __launch_bounds__(256)
void gemm_kernel(const float* __restrict__ x,
                 const float* __restrict__ W,
                 const float* __restrict__ b,
                 float* __restrict__ out, int N) {
    __shared__ float Ws[D * D];   // transposed: Ws[i*64 + o] = W[o][i]
    __shared__ float Bs[D];

    for (int t = threadIdx.x; t < D * D; t += blockDim.x) {
        int o = t >> 6;
        int i = t & 63;
        Ws[i * D + o] = W[t];
    }
    if (threadIdx.x < D) Bs[threadIdx.x] = b[threadIdx.x];
    __syncthreads();

    int n = blockIdx.x * blockDim.x + threadIdx.x;
    if (n >= N) return;

    float4 acc[16];
#pragma unroll
    for (int j = 0; j < 16; j++) acc[j] = make_float4(0.f, 0.f, 0.f, 0.f);

    const float4* xr  = (const float4*)x + (size_t)n * 16;
    const float4* Ws4 = (const float4*)Ws;

#pragma unroll 1
    for (int i4 = 0; i4 < 16; i4++) {
        float4 xv = xr[i4];
        float xs[4] = {xv.x, xv.y, xv.z, xv.w};
#pragma unroll
        for (int k = 0; k < 4; k++) {
            float xk = xs[k];
            const float4* wrow = Ws4 + (size_t)(i4 * 4 + k) * 16;
#pragma unroll
            for (int j = 0; j < 16; j++) {
                float4 w = wrow[j];
                acc[j].x = fmaf(xk, w.x, acc[j].x);
                acc[j].y = fmaf(xk, w.y, acc[j].y);
                acc[j].z = fmaf(xk, w.z, acc[j].z);
                acc[j].w = fmaf(xk, w.w, acc[j].w);
            }
        }
    }

    float dv = g_dinv[n];
    float sl = dv * dv;
    float4* hr   = (float4*)g_h + (size_t)n * 16;
    float4* orow = (float4*)out + (size_t)n * 16;
    const float4* Bs4 = (const float4*)Bs;
#pragma unroll
    for (int j = 0; j < 16; j++) {
        hr[j] = acc[j];
        float4 bb = Bs4[j];
        float4 ov;
        ov.x = fmaf(acc[j].x, sl, bb.x);
        ov.y = fmaf(acc[j].y, sl, bb.y);
        ov.z = fmaf(acc[j].z, sl, bb.z);
        ov.w = fmaf(acc[j].w, sl, bb.w);
        orow[j] = ov;
    }
}

// ---------------------------------------------------------------------------
// 5) Edge scatter: out[dst] += h[src] * (dinv[src]*dinv[dst])
//    16 threads per edge, one float4 per thread, vector red (4x fewer L2
//    atomic ops than scalar atomicAdd).
// ---------------------------------------------------------------------------
__global__ __launch_bounds__(256)
void scatter_kernel(const int* __restrict__ ei,
                    float* __restrict__ out, int E) {
    long long gid = (long long)blockIdx.x * blockDim.x + threadIdx.x;
    int e = (int)(gid >> 4);
    int l = (int)(gid & 15);
    if (e >= E) return;

    int s = ei[e];        // src
    int d = ei[E + e];    // dst
    float norm = g_dinv[s] * g_dinv[d];

    float4 v = ((const float4*)g_h)[(size_t)s * 16 + l];
    v.x *= norm; v.y *= norm; v.z *= norm; v.w *= norm;

    float* o = out + ((size_t)d * D + l * 4);
    asm volatile("red.global.add.v4.f32 [%0], {%1, %2, %3, %4};"
                 :: "l"(o), "f"(v.x), "f"(v.y), "f"(v.z), "f"(v.w)
                 : "memory");
}

// ---------------------------------------------------------------------------
extern "C" void kernel_launch(void* const* d_in, const int* in_sizes, int n_in,
                              void* d_out, int out_size) {
    const float* x  = (const float*)d_in[0];
    const int*   ei = (const int*)d_in[1];
    const float* W  = (const float*)d_in[2];
    const float* b  = (const float*)d_in[3];
    float*       out = (float*)d_out;

    int N = in_sizes[0] / D;   // 100000
    int E = in_sizes[1] / 2;   // 1000000

    int nb_n = (N + 255) / 256;
    int nb_e = (E + 255) / 256;

    deg_init_kernel<<<nb_n, 256>>>(N);
    deg_acc_kernel<<<nb_e, 256>>>(ei, E);
    dinv_kernel<<<nb_n, 256>>>(N);
    gemm_kernel<<<nb_n, 256>>>(x, W, b, out, N);

    long long total = (long long)E * 16;
    int nb_s = (int)((total + 255) / 256);
    scatter_kernel<<<nb_s, 256>>>(ei, out, E);
}

// round 3
// speedup vs baseline: 1.0616x; 1.0616x over previous
#include <cuda_runtime.h>

#define MAX_N 100000
#define D 64

// Scratch (device globals: sanctioned alternative to cudaMalloc)
__device__ float g_h[MAX_N * D];     // h = x @ W^T
__device__ float g_deg[MAX_N];
__device__ float g_dinv[MAX_N];

// ---------------------------------------------------------------------------
// 1) degree init: every node gets a self-loop -> deg starts at 1
// ---------------------------------------------------------------------------
__global__ void deg_init_kernel(int N4) {
    int i = blockIdx.x * blockDim.x + threadIdx.x;
    if (i < N4) ((float4*)g_deg)[i] = make_float4(1.f, 1.f, 1.f, 1.f);
}

// 2) accumulate in-degree over edge dst (edge_index is int32)
__global__ void deg_acc_kernel(const int* __restrict__ ei, int E) {
    int e = blockIdx.x * blockDim.x + threadIdx.x;
    if (e < E) {
        int d = ei[E + e];   // edge_index[1][e]
        atomicAdd(&g_deg[d], 1.0f);
    }
}

// ---------------------------------------------------------------------------
// 3) GEMM: h[n][o] = sum_k x[n][k] * W[o][k]
//    Register tiling: 2 nodes x 32 outputs per thread, packed f32x2 FFMA2.
//    Epilogue: dinv[n] = rsqrt(deg[n]) (fused, replaces dinv_kernel),
//              out[n][o] = h[n][o]*dinv[n]^2 + b[o]  (self-loop + bias,
//              fully initializes the poisoned output buffer).
// ---------------------------------------------------------------------------
__global__ __launch_bounds__(256, 2)
void gemm_kernel(const float* __restrict__ x,
                 const float* __restrict__ W,
                 const float* __restrict__ bias,
                 float* __restrict__ out, int N) {
    __shared__ float Ws[D * D];   // Ws[k*64 + o] = W[o][k]  (transposed)

    for (int t = threadIdx.x; t < D * D; t += 256) {
        int o = t >> 6;
        int k = t & 63;
        Ws[k * D + o] = W[t];
    }
    __syncthreads();

    int tid  = threadIdx.x;
    int half = tid >> 7;          // output half: cols [0,32) or [32,64)
    int g    = tid & 127;         // node-pair index within block
    int n0   = blockIdx.x * 256 + g * 2;
    if (n0 >= N) return;
    int n1 = (n0 + 1 < N) ? (n0 + 1) : n0;   // N is even here; generic guard

    // acc[node][m]: 16 f32x2 = 32 outputs per node
    unsigned long long acc[2][16];
#pragma unroll
    for (int j = 0; j < 2; j++)
#pragma unroll
        for (int m = 0; m < 16; m++) acc[j][m] = 0ULL;

    const float4* xr0 = (const float4*)(x + (size_t)n0 * D);
    const float4* xr1 = (const float4*)(x + (size_t)n1 * D);
    const ulonglong2* wsb = (const ulonglong2*)Ws;   // 16B granules

#pragma unroll 1
    for (int i4 = 0; i4 < 16; i4++) {
        float4 xa = xr0[i4];
        float4 xb = xr1[i4];
        float xs0[4] = {xa.x, xa.y, xa.z, xa.w};
        float xs1[4] = {xb.x, xb.y, xb.z, xb.w};
#pragma unroll
        for (int kk = 0; kk < 4; kk++) {
            int k = i4 * 4 + kk;
            unsigned long long xx0, xx1;
            asm("mov.b64 %0, {%1, %1};" : "=l"(xx0) : "f"(xs0[kk]));
            asm("mov.b64 %0, {%1, %1};" : "=l"(xx1) : "f"(xs1[kk]));
            // w row for this k, this output half: 32 floats = 8 x 16B
            const ulonglong2* wp = wsb + (size_t)k * 16 + half * 8;
#pragma unroll
            for (int m = 0; m < 8; m++) {
                ulonglong2 wv = wp[m];   // broadcast LDS.128 (warp-uniform)
                asm("fma.rn.f32x2 %0, %1, %2, %0;"
                    : "+l"(acc[0][2 * m])     : "l"(xx0), "l"(wv.x));
                asm("fma.rn.f32x2 %0, %1, %2, %0;"
                    : "+l"(acc[0][2 * m + 1]) : "l"(xx0), "l"(wv.y));
                asm("fma.rn.f32x2 %0, %1, %2, %0;"
                    : "+l"(acc[1][2 * m])     : "l"(xx1), "l"(wv.x));
                asm("fma.rn.f32x2 %0, %1, %2, %0;"
                    : "+l"(acc[1][2 * m + 1]) : "l"(xx1), "l"(wv.y));
            }
        }
    }

    // Epilogue
    const float* brow = bias + half * 32;
#pragma unroll
    for (int j = 0; j < 2; j++) {
        int n = (j == 0) ? n0 : n0 + 1;
        if (n >= N) break;
        float dv = rsqrtf(g_deg[n]);
        g_dinv[n] = dv;               // both halves write same value: benign
        float sl = dv * dv;
        float* hrow = g_h + (size_t)n * D + half * 32;
        float* orow = out + (size_t)n * D + half * 32;
#pragma unroll
        for (int m = 0; m < 8; m++) {
            float f0, f1, f2, f3;
            asm("mov.b64 {%0, %1}, %2;" : "=f"(f0), "=f"(f1) : "l"(acc[j][2 * m]));
            asm("mov.b64 {%0, %1}, %2;" : "=f"(f2), "=f"(f3) : "l"(acc[j][2 * m + 1]));
            ((float4*)hrow)[m] = make_float4(f0, f1, f2, f3);
            float4 bb = ((const float4*)brow)[m];
            float4 ov;
            ov.x = fmaf(f0, sl, bb.x);
            ov.y = fmaf(f1, sl, bb.y);
            ov.z = fmaf(f2, sl, bb.z);
            ov.w = fmaf(f3, sl, bb.w);
            ((float4*)orow)[m] = ov;
        }
    }
}

// ---------------------------------------------------------------------------
// 4) Edge scatter: out[dst] += h[src] * (dinv[src]*dinv[dst])
//    16 threads per edge, one float4 per thread, vector red.
// ---------------------------------------------------------------------------
__global__ __launch_bounds__(256)
void scatter_kernel(const int* __restrict__ ei,
                    float* __restrict__ out, int E) {
    long long gid = (long long)blockIdx.x * blockDim.x + threadIdx.x;
    int e = (int)(gid >> 4);
    int l = (int)(gid & 15);
    if (e >= E) return;

    int s = ei[e];        // src
    int d = ei[E + e];    // dst
    float norm = g_dinv[s] * g_dinv[d];

    float4 v = ((const float4*)g_h)[(size_t)s * 16 + l];
    v.x *= norm; v.y *= norm; v.z *= norm; v.w *= norm;

    float* o = out + ((size_t)d * D + l * 4);
    asm volatile("red.global.add.v4.f32 [%0], {%1, %2, %3, %4};"
                 :: "l"(o), "f"(v.x), "f"(v.y), "f"(v.z), "f"(v.w)
                 : "memory");
}

// ---------------------------------------------------------------------------
extern "C" void kernel_launch(void* const* d_in, const int* in_sizes, int n_in,
                              void* d_out, int out_size) {
    const float* x  = (const float*)d_in[0];
    const int*   ei = (const int*)d_in[1];
    const float* W  = (const float*)d_in[2];
    const float* b  = (const float*)d_in[3];
    float*       out = (float*)d_out;

    int N = in_sizes[0] / D;   // 100000
    int E = in_sizes[1] / 2;   // 1000000

    int N4 = N / 4;            // N divisible by 4
    deg_init_kernel<<<(N4 + 255) / 256, 256>>>(N4);
    deg_acc_kernel<<<(E + 255) / 256, 256>>>(ei, E);
    gemm_kernel<<<(N + 255) / 256, 256>>>(x, W, b, out, N);

    long long total = (long long)E * 16;
    int nb_s = (int)((total + 255) / 256);
    scatter_kernel<<<nb_s, 256>>>(ei, out, E);
}